// round 4
// baseline (speedup 1.0000x reference)
#include <cuda_runtime.h>
#include <math.h>

// Problem constants
#define SEQ     512
#define INDIM   512
#define HID     1024
#define GATES   4096   // 4*HID, PyTorch gate order i,f,g,o
#define LAYERS  4

// Scan kernel config
#define NCTA    128
#define NTHR    256
#define UPC     8      // h-units per CTA (one per warp)

// ---------------- device scratch (no allocations allowed) ----------------
__device__ float    g_gx[SEQ * GATES];   // 8 MB, per-layer input-GEMM result
__device__ float    g_h0[SEQ * HID];     // 2 MB ping
__device__ float    g_h1[SEQ * HID];     // 2 MB pong
__device__ unsigned g_bar[LAYERS];       // per-layer barrier counters

__device__ __forceinline__ float sigmoidf_(float x) {
    return 1.0f / (1.0f + expf(-x));
}

// ---------------- init: zero barrier counters ----------------
__global__ void init_bars() {
    if (threadIdx.x < LAYERS) g_bar[threadIdx.x] = 0u;
}

// ---- input GEMM: out[M=512][N=4096] = A[M][K](row stride lda) * W[N][K]^T + b1+b2 ----
#define GBM 64
#define GBN 64
#define GBK 16
__global__ __launch_bounds__(256)
void gemm_gx(const float* __restrict__ A,   // [512, K] rows strided by lda
             int lda,
             const float* __restrict__ Wt,  // [4096, K] row-major
             const float* __restrict__ b1,  // [4096]
             const float* __restrict__ b2,  // [4096]
             float* __restrict__ out,       // [512, 4096]
             int K)
{
    __shared__ float As[GBK][GBM + 4];
    __shared__ float Bs[GBK][GBN + 4];

    const int bm = blockIdx.y * GBM;
    const int bn = blockIdx.x * GBN;
    const int tid = threadIdx.x;
    const int tx = tid & 15;          // 0..15
    const int ty = tid >> 4;          // 0..15
    const int lr = tid >> 2;          // 0..63 : row within tile for loading
    const int lk = (tid & 3) * 4;     // 0,4,8,12 : k offset within tile

    float acc[4][4];
#pragma unroll
    for (int i = 0; i < 4; i++)
#pragma unroll
        for (int j = 0; j < 4; j++) acc[i][j] = 0.0f;

    for (int k0 = 0; k0 < K; k0 += GBK) {
        float4 a = *(const float4*)(A  + (size_t)(bm + lr) * lda + k0 + lk);
        float4 w = *(const float4*)(Wt + (size_t)(bn + lr) * K   + k0 + lk);
        As[lk + 0][lr] = a.x; As[lk + 1][lr] = a.y; As[lk + 2][lr] = a.z; As[lk + 3][lr] = a.w;
        Bs[lk + 0][lr] = w.x; Bs[lk + 1][lr] = w.y; Bs[lk + 2][lr] = w.z; Bs[lk + 3][lr] = w.w;
        __syncthreads();
#pragma unroll
        for (int k = 0; k < GBK; k++) {
            float4 av = *(const float4*)&As[k][ty * 4];
            float4 bv = *(const float4*)&Bs[k][tx * 4];
            acc[0][0] += av.x * bv.x; acc[0][1] += av.x * bv.y; acc[0][2] += av.x * bv.z; acc[0][3] += av.x * bv.w;
            acc[1][0] += av.y * bv.x; acc[1][1] += av.y * bv.y; acc[1][2] += av.y * bv.z; acc[1][3] += av.y * bv.w;
            acc[2][0] += av.z * bv.x; acc[2][1] += av.z * bv.y; acc[2][2] += av.z * bv.z; acc[2][3] += av.z * bv.w;
            acc[3][0] += av.w * bv.x; acc[3][1] += av.w * bv.y; acc[3][2] += av.w * bv.z; acc[3][3] += av.w * bv.w;
        }
        __syncthreads();
    }

    float4 bb1 = *(const float4*)(b1 + bn + tx * 4);
    float4 bb2 = *(const float4*)(b2 + bn + tx * 4);
    float bias[4] = { bb1.x + bb2.x, bb1.y + bb2.y, bb1.z + bb2.z, bb1.w + bb2.w };
#pragma unroll
    for (int i = 0; i < 4; i++) {
        size_t row = (size_t)(bm + ty * 4 + i) * GATES + bn + tx * 4;
#pragma unroll
        for (int j = 0; j < 4; j++)
            out[row + j] = acc[i][j] + bias[j];
    }
}

// ---------------- recurrent scan: 512 sequential steps, persistent grid ----------------
// Each CTA owns 8 h-units (one per warp). The warp's 4 gate rows (i,f,g,o) of W_hh
// live in registers: lane group (gate = lane>>3) x k-chunk (kk = lane&7, 128 elems).
__global__ __launch_bounds__(NTHR, 1)
void lstm_scan(const float* __restrict__ w_hh_l,   // [4096,1024] this layer
               const float* __restrict__ gx,       // [512,4096] input-gemm+bias
               float* __restrict__ h_out,          // [512,1024]
               unsigned* __restrict__ bar)
{
    __shared__ float sh[HID];   // 4KB staged h_{t-1}

    const int cta  = blockIdx.x;
    const int tid  = threadIdx.x;
    const int warp = tid >> 5;            // 0..7 -> unit within CTA
    const int lane = tid & 31;
    const int gate = lane >> 3;           // 0..3 (i,f,g,o)
    const int kk   = lane & 7;            // k-chunk 0..7 (128 elems each)
    const int unit = cta * UPC + warp;    // 0..1023
    const int wrow = gate * HID + unit;   // row in W_hh

    // Load 128 weights (this lane's k-chunk of its gate row) into registers.
    float4 W[32];
    {
        const float4* wp = (const float4*)(w_hh_l + (size_t)wrow * HID + kk * 128);
#pragma unroll
        for (int i = 0; i < 32; i++) W[i] = __ldg(wp + i);
    }

    float c = 0.0f;   // cell state (valid on lane 0 of each warp)

    for (int t = 0; t < SEQ; t++) {
        // prefetch gx for this gate row (independent of h recurrence)
        float gxv = 0.0f;
        if (kk == 0) gxv = __ldg(&gx[(size_t)t * GATES + wrow]);

        float acc = 0.0f;
        if (t > 0) {
            // stage h_{t-1} (4KB) into SMEM, L2-coherent loads
            const float4* hp = (const float4*)(h_out + (size_t)(t - 1) * HID);
            float4 v = __ldcg(hp + tid);
            ((float4*)sh)[tid] = v;
            __syncthreads();

            const float4* hs = (const float4*)(sh + kk * 128);
#pragma unroll
            for (int i = 0; i < 32; i++) {
                float4 hv = hs[i];
                acc += W[i].x * hv.x + W[i].y * hv.y + W[i].z * hv.z + W[i].w * hv.w;
            }
        }

        // reduce the 8 lanes of each gate group
        acc += __shfl_down_sync(0xffffffffu, acc, 4);
        acc += __shfl_down_sync(0xffffffffu, acc, 2);
        acc += __shfl_down_sync(0xffffffffu, acc, 1);

        float gval = acc + gxv;   // meaningful on kk==0 lanes (0,8,16,24)
        float gi = __shfl_sync(0xffffffffu, gval, 0);
        float gf = __shfl_sync(0xffffffffu, gval, 8);
        float gg = __shfl_sync(0xffffffffu, gval, 16);
        float go = __shfl_sync(0xffffffffu, gval, 24);

        if (lane == 0) {
            c = sigmoidf_(gf) * c + sigmoidf_(gi) * tanhf(gg);
            float h = sigmoidf_(go) * tanhf(c);
            h_out[(size_t)t * HID + unit] = h;
            __threadfence();   // release this warp's h write (device scope)
        }

        // grid barrier: monotonic counter, target = (t+1)*NCTA
        __syncthreads();
        if (tid == 0) {
            atomicAdd(bar, 1u);
            const unsigned target = (unsigned)(t + 1) * NCTA;
            while (*(volatile unsigned*)bar < target) { __nanosleep(32); }
            __threadfence();   // acquire side
        }
        __syncthreads();
    }
}

// ---------------- final FC: out[t] = sum_j sigmoid(h[t][j]) * fcw[j] + fcb ----------------
__global__ void final_fc(const float* __restrict__ h,
                         const float* __restrict__ fcw,
                         const float* __restrict__ fcb,
                         float* __restrict__ out)
{
    const int t = blockIdx.x;
    const int tid = threadIdx.x;   // 128 threads
    float s = 0.0f;
    for (int j = tid; j < HID; j += 128)
        s += fcw[j] * sigmoidf_(h[(size_t)t * HID + j]);
    s += __shfl_down_sync(0xffffffffu, s, 16);
    s += __shfl_down_sync(0xffffffffu, s, 8);
    s += __shfl_down_sync(0xffffffffu, s, 4);
    s += __shfl_down_sync(0xffffffffu, s, 2);
    s += __shfl_down_sync(0xffffffffu, s, 1);
    __shared__ float red[4];
    if ((tid & 31) == 0) red[tid >> 5] = s;
    __syncthreads();
    if (tid == 0) out[t] = red[0] + red[1] + red[2] + red[3] + fcb[0];
}

// ---------------- launch ----------------
extern "C" void kernel_launch(void* const* d_in, const int* in_sizes, int n_in,
                              void* d_out, int out_size)
{
    const float* x         = (const float*)d_in[0];  // [512,64,512]
    const float* w_ih0     = (const float*)d_in[1];  // [4096,512]
    const float* w_ih_rest = (const float*)d_in[2];  // [3,4096,1024]
    const float* w_hh      = (const float*)d_in[3];  // [4,4096,1024]
    const float* b_ih      = (const float*)d_in[4];  // [4,4096]
    const float* b_hh      = (const float*)d_in[5];  // [4,4096]
    const float* fc_w      = (const float*)d_in[6];  // [1,1024]
    const float* fc_b      = (const float*)d_in[7];  // [1]
    float* out             = (float*)d_out;          // [512,1]

    float *gx, *h0, *h1; unsigned* bar;
    cudaGetSymbolAddress((void**)&gx,  g_gx);
    cudaGetSymbolAddress((void**)&h0,  g_h0);
    cudaGetSymbolAddress((void**)&h1,  g_h1);
    cudaGetSymbolAddress((void**)&bar, g_bar);

    init_bars<<<1, 32>>>();

    dim3 ggrid(GATES / GBN, SEQ / GBM);   // (64, 8)

    // layer 0: gx from x (batch row 63, lda = 64*512), scan -> h1
    gemm_gx<<<ggrid, 256>>>(x + (size_t)63 * INDIM, 64 * INDIM,
                            w_ih0, b_ih, b_hh, gx, INDIM);
    lstm_scan<<<NCTA, NTHR>>>(w_hh, gx, h1, bar + 0);

    // layer 1: h1 -> h0
    gemm_gx<<<ggrid, 256>>>(h1, HID, w_ih_rest,
                            b_ih + GATES, b_hh + GATES, gx, HID);
    lstm_scan<<<NCTA, NTHR>>>(w_hh + (size_t)1 * GATES * HID, gx, h0, bar + 1);

    // layer 2: h0 -> h1
    gemm_gx<<<ggrid, 256>>>(h0, HID, w_ih_rest + (size_t)1 * GATES * HID,
                            b_ih + 2 * GATES, b_hh + 2 * GATES, gx, HID);
    lstm_scan<<<NCTA, NTHR>>>(w_hh + (size_t)2 * GATES * HID, gx, h1, bar + 2);

    // layer 3: h1 -> h0
    gemm_gx<<<ggrid, 256>>>(h1, HID, w_ih_rest + (size_t)2 * GATES * HID,
                            b_ih + 3 * GATES, b_hh + 3 * GATES, gx, HID);
    lstm_scan<<<NCTA, NTHR>>>(w_hh + (size_t)3 * GATES * HID, gx, h0, bar + 3);

    final_fc<<<SEQ, 128>>>(h0, fc_w, fc_b, out);
}

// round 5
// speedup vs baseline: 1.0093x; 1.0093x over previous
#include <cuda_runtime.h>
#include <math.h>

// Problem constants
#define SEQ     512
#define INDIM   512
#define HID     1024
#define GATES   4096   // 4*HID, PyTorch gate order i,f,g,o
#define LAYERS  4

// Scan kernel config
#define NCTA    128
#define NTHR    256
#define UPC     8      // h-units per CTA (one per warp)

// ---------------- device scratch (no allocations allowed) ----------------
__device__ float    g_gx[SEQ * GATES];        // 8 MB, per-layer input-GEMM result
__device__ float    g_h0[SEQ * HID];          // 2 MB ping
__device__ float    g_h1[SEQ * HID];          // 2 MB pong
__device__ unsigned g_flags[LAYERS * NCTA];   // per-CTA monotonic progress flags

__device__ __forceinline__ float sigm_fast(float x) {
    return 1.0f / (1.0f + __expf(-x));
}
__device__ __forceinline__ float tanh_fast(float x) {
    // tanh(x) = 1 - 2/(1+e^{2x}); exact limits at +-inf
    return 1.0f - 2.0f / (1.0f + __expf(2.0f * x));
}

// ---------------- init: zero progress flags ----------------
__global__ void init_flags() {
    int i = blockIdx.x * blockDim.x + threadIdx.x;
    if (i < LAYERS * NCTA) g_flags[i] = 0u;
}

// ---- input GEMM: out[M=512][N=4096] = A[M][K](row stride lda) * W[N][K]^T + b1+b2 ----
#define GBM 64
#define GBN 64
#define GBK 16
__global__ __launch_bounds__(256)
void gemm_gx(const float* __restrict__ A,   // [512, K] rows strided by lda
             int lda,
             const float* __restrict__ Wt,  // [4096, K] row-major
             const float* __restrict__ b1,  // [4096]
             const float* __restrict__ b2,  // [4096]
             float* __restrict__ out,       // [512, 4096]
             int K)
{
    __shared__ float As[GBK][GBM + 4];
    __shared__ float Bs[GBK][GBN + 4];

    const int bm = blockIdx.y * GBM;
    const int bn = blockIdx.x * GBN;
    const int tid = threadIdx.x;
    const int tx = tid & 15;          // 0..15
    const int ty = tid >> 4;          // 0..15
    const int lr = tid >> 2;          // 0..63 : row within tile for loading
    const int lk = (tid & 3) * 4;     // 0,4,8,12 : k offset within tile

    float acc[4][4];
#pragma unroll
    for (int i = 0; i < 4; i++)
#pragma unroll
        for (int j = 0; j < 4; j++) acc[i][j] = 0.0f;

    for (int k0 = 0; k0 < K; k0 += GBK) {
        float4 a = *(const float4*)(A  + (size_t)(bm + lr) * lda + k0 + lk);
        float4 w = *(const float4*)(Wt + (size_t)(bn + lr) * K   + k0 + lk);
        As[lk + 0][lr] = a.x; As[lk + 1][lr] = a.y; As[lk + 2][lr] = a.z; As[lk + 3][lr] = a.w;
        Bs[lk + 0][lr] = w.x; Bs[lk + 1][lr] = w.y; Bs[lk + 2][lr] = w.z; Bs[lk + 3][lr] = w.w;
        __syncthreads();
#pragma unroll
        for (int k = 0; k < GBK; k++) {
            float4 av = *(const float4*)&As[k][ty * 4];
            float4 bv = *(const float4*)&Bs[k][tx * 4];
            acc[0][0] += av.x * bv.x; acc[0][1] += av.x * bv.y; acc[0][2] += av.x * bv.z; acc[0][3] += av.x * bv.w;
            acc[1][0] += av.y * bv.x; acc[1][1] += av.y * bv.y; acc[1][2] += av.y * bv.z; acc[1][3] += av.y * bv.w;
            acc[2][0] += av.z * bv.x; acc[2][1] += av.z * bv.y; acc[2][2] += av.z * bv.z; acc[2][3] += av.z * bv.w;
            acc[3][0] += av.w * bv.x; acc[3][1] += av.w * bv.y; acc[3][2] += av.w * bv.z; acc[3][3] += av.w * bv.w;
        }
        __syncthreads();
    }

    float4 bb1 = *(const float4*)(b1 + bn + tx * 4);
    float4 bb2 = *(const float4*)(b2 + bn + tx * 4);
    float bias[4] = { bb1.x + bb2.x, bb1.y + bb2.y, bb1.z + bb2.z, bb1.w + bb2.w };
#pragma unroll
    for (int i = 0; i < 4; i++) {
        size_t row = (size_t)(bm + ty * 4 + i) * GATES + bn + tx * 4;
#pragma unroll
        for (int j = 0; j < 4; j++)
            out[row + j] = acc[i][j] + bias[j];
    }
}

// ---------------- recurrent scan: 512 sequential steps, persistent grid ----------------
// Each CTA owns 8 h-units (one per warp). The warp's 4 gate rows (i,f,g,o) of W_hh
// live in registers: lane group (gate = lane>>3) x k-chunk (kk = lane&7, 128 elems).
//
// Sync: per-CTA monotonic flags. After writing h[t], CTA does
//   STG h -> __syncthreads -> st.release.gpu flag[cta] = t+1   (cumulative release)
// At step t (t>0) every CTA polls all NCTA flags with ld.acquire.gpu until min >= t.
// No atomics, no nanosleep, no convergent barrier: CTAs may skew; rows are disjoint.
__global__ __launch_bounds__(NTHR, 1)
void lstm_scan(const float* __restrict__ w_hh_l,   // [4096,1024] this layer
               const float* __restrict__ gx,       // [512,4096] input-gemm+bias
               float* __restrict__ h_out,          // [512,1024]
               unsigned* __restrict__ flags)       // [NCTA]
{
    __shared__ float sh[HID];   // 4KB staged h_{t-1}

    const int cta  = blockIdx.x;
    const int tid  = threadIdx.x;
    const int warp = tid >> 5;            // 0..7 -> unit within CTA
    const int lane = tid & 31;
    const int gate = lane >> 3;           // 0..3 (i,f,g,o)
    const int kk   = lane & 7;            // k-chunk 0..7 (128 elems each)
    const int unit = cta * UPC + warp;    // 0..1023
    const int wrow = gate * HID + unit;   // row in W_hh

    // Load 128 weights (this lane's k-chunk of its gate row) into registers.
    float4 W[32];
    {
        const float4* wp = (const float4*)(w_hh_l + (size_t)wrow * HID + kk * 128);
#pragma unroll
        for (int i = 0; i < 32; i++) W[i] = __ldg(wp + i);
    }

    float c = 0.0f;   // cell state (valid on lane 0 of each warp)

    for (int t = 0; t < SEQ; t++) {
        // prefetch gx for this gate row (independent of the recurrence)
        float gxv = 0.0f;
        if (kk == 0) gxv = __ldg(&gx[(size_t)t * GATES + wrow]);

        float acc = 0.0f;
        if (t > 0) {
            // wait until every producer CTA has published h[t-1]
            unsigned v = (unsigned)t;   // threads >= NCTA trivially pass
            const unsigned* fp = flags + tid;
            do {
                if (tid < NCTA)
                    asm volatile("ld.acquire.gpu.global.u32 %0, [%1];"
                                 : "=r"(v) : "l"(fp));
            } while (__syncthreads_and(v >= (unsigned)t) == 0);

            // stage h_{t-1} (4KB) into SMEM, L2-only loads
            const float4* hp = (const float4*)(h_out + (size_t)(t - 1) * HID);
            float4 hv4 = __ldcg(hp + tid);
            ((float4*)sh)[tid] = hv4;
            __syncthreads();

            const float4* hs = (const float4*)(sh + kk * 128);
#pragma unroll
            for (int i = 0; i < 32; i++) {
                float4 hv = hs[i];
                acc += W[i].x * hv.x + W[i].y * hv.y + W[i].z * hv.z + W[i].w * hv.w;
            }
        }

        // reduce the 8 lanes of each gate group
        acc += __shfl_down_sync(0xffffffffu, acc, 4);
        acc += __shfl_down_sync(0xffffffffu, acc, 2);
        acc += __shfl_down_sync(0xffffffffu, acc, 1);

        float gval = acc + gxv;   // meaningful on kk==0 lanes (0,8,16,24)

        // activations in parallel on the 4 group-leader lanes (g-gate -> tanh)
        float act = (gate == 2) ? tanh_fast(gval) : sigm_fast(gval);
        float ai = __shfl_sync(0xffffffffu, act, 0);
        float af = __shfl_sync(0xffffffffu, act, 8);
        float ag = __shfl_sync(0xffffffffu, act, 16);
        float ao = __shfl_sync(0xffffffffu, act, 24);

        if (lane == 0) {
            c = af * c + ai * ag;
            float h = ao * tanh_fast(c);
            h_out[(size_t)t * HID + unit] = h;
        }

        // publish: all warps' h writes happen-before the release store (via bar)
        __syncthreads();
        if (tid == 0) {
            unsigned nv = (unsigned)(t + 1);
            asm volatile("st.release.gpu.global.u32 [%0], %1;"
                         :: "l"(flags + cta), "r"(nv) : "memory");
        }
    }
}

// ---------------- final FC: out[t] = sum_j sigmoid(h[t][j]) * fcw[j] + fcb ----------------
__global__ void final_fc(const float* __restrict__ h,
                         const float* __restrict__ fcw,
                         const float* __restrict__ fcb,
                         float* __restrict__ out)
{
    const int t = blockIdx.x;
    const int tid = threadIdx.x;   // 128 threads
    float s = 0.0f;
    for (int j = tid; j < HID; j += 128)
        s += fcw[j] * sigm_fast(h[(size_t)t * HID + j]);
    s += __shfl_down_sync(0xffffffffu, s, 16);
    s += __shfl_down_sync(0xffffffffu, s, 8);
    s += __shfl_down_sync(0xffffffffu, s, 4);
    s += __shfl_down_sync(0xffffffffu, s, 2);
    s += __shfl_down_sync(0xffffffffu, s, 1);
    __shared__ float red[4];
    if ((tid & 31) == 0) red[tid >> 5] = s;
    __syncthreads();
    if (tid == 0) out[t] = red[0] + red[1] + red[2] + red[3] + fcb[0];
}

// ---------------- launch ----------------
extern "C" void kernel_launch(void* const* d_in, const int* in_sizes, int n_in,
                              void* d_out, int out_size)
{
    const float* x         = (const float*)d_in[0];  // [512,64,512]
    const float* w_ih0     = (const float*)d_in[1];  // [4096,512]
    const float* w_ih_rest = (const float*)d_in[2];  // [3,4096,1024]
    const float* w_hh      = (const float*)d_in[3];  // [4,4096,1024]
    const float* b_ih      = (const float*)d_in[4];  // [4,4096]
    const float* b_hh      = (const float*)d_in[5];  // [4,4096]
    const float* fc_w      = (const float*)d_in[6];  // [1,1024]
    const float* fc_b      = (const float*)d_in[7];  // [1]
    float* out             = (float*)d_out;          // [512,1]

    float *gx, *h0, *h1; unsigned* flags;
    cudaGetSymbolAddress((void**)&gx,    g_gx);
    cudaGetSymbolAddress((void**)&h0,    g_h0);
    cudaGetSymbolAddress((void**)&h1,    g_h1);
    cudaGetSymbolAddress((void**)&flags, g_flags);

    init_flags<<<(LAYERS * NCTA + 255) / 256, 256>>>();

    dim3 ggrid(GATES / GBN, SEQ / GBM);   // (64, 8)

    // layer 0: gx from x (batch row 63, lda = 64*512), scan -> h1
    gemm_gx<<<ggrid, 256>>>(x + (size_t)63 * INDIM, 64 * INDIM,
                            w_ih0, b_ih, b_hh, gx, INDIM);
    lstm_scan<<<NCTA, NTHR>>>(w_hh, gx, h1, flags + 0 * NCTA);

    // layer 1: h1 -> h0
    gemm_gx<<<ggrid, 256>>>(h1, HID, w_ih_rest,
                            b_ih + GATES, b_hh + GATES, gx, HID);
    lstm_scan<<<NCTA, NTHR>>>(w_hh + (size_t)1 * GATES * HID, gx, h0, flags + 1 * NCTA);

    // layer 2: h0 -> h1
    gemm_gx<<<ggrid, 256>>>(h0, HID, w_ih_rest + (size_t)1 * GATES * HID,
                            b_ih + 2 * GATES, b_hh + 2 * GATES, gx, HID);
    lstm_scan<<<NCTA, NTHR>>>(w_hh + (size_t)2 * GATES * HID, gx, h1, flags + 2 * NCTA);

    // layer 3: h1 -> h0
    gemm_gx<<<ggrid, 256>>>(h1, HID, w_ih_rest + (size_t)2 * GATES * HID,
                            b_ih + 3 * GATES, b_hh + 3 * GATES, gx, HID);
    lstm_scan<<<NCTA, NTHR>>>(w_hh + (size_t)3 * GATES * HID, gx, h0, flags + 3 * NCTA);

    final_fc<<<SEQ, 128>>>(h0, fc_w, fc_b, out);
}

// round 6
// speedup vs baseline: 1.0524x; 1.0426x over previous
#include <cuda_runtime.h>
#include <math.h>

// Problem constants
#define SEQ     512
#define INDIM   512
#define HID     1024
#define GATES   4096   // 4*HID, PyTorch gate order i,f,g,o
#define LAYERS  4

// Scan kernel config
#define NCTA    128
#define NTHR    256
#define UPC     8      // h-units per CTA (one per warp)
#define FPAD    32     // flag padding: one 128B line per flag

// ---------------- device scratch (no allocations allowed) ----------------
__device__ float    g_gx[SEQ * GATES];               // 8 MB, per-layer input-GEMM result
__device__ float    g_h0[SEQ * HID];                 // 2 MB ping
__device__ float    g_h1[SEQ * HID];                 // 2 MB pong
__device__ unsigned g_flags[LAYERS * NCTA * FPAD];   // padded per-CTA progress flags

__device__ __forceinline__ float sigm_fast(float x) {
    return 1.0f / (1.0f + __expf(-x));
}
__device__ __forceinline__ float tanh_fast(float x) {
    return 1.0f - 2.0f / (1.0f + __expf(2.0f * x));
}

// ---------------- init: zero progress flags ----------------
__global__ void init_flags() {
    int i = blockIdx.x * blockDim.x + threadIdx.x;
    if (i < LAYERS * NCTA * FPAD) g_flags[i] = 0u;
}

// no-op spacer so ncu (-s 5 -c 1) lands on lstm_scan as launch #6
__global__ void noop_k() {}

// ---- input GEMM: out[M=512][N=4096] = A[M][K](row stride lda) * W[N][K]^T + b1+b2 ----
#define GBM 64
#define GBN 64
#define GBK 16
__global__ __launch_bounds__(256)
void gemm_gx(const float* __restrict__ A,   // [512, K] rows strided by lda
             int lda,
             const float* __restrict__ Wt,  // [4096, K] row-major
             const float* __restrict__ b1,  // [4096]
             const float* __restrict__ b2,  // [4096]
             float* __restrict__ out,       // [512, 4096]
             int K)
{
    __shared__ float As[GBK][GBM + 4];
    __shared__ float Bs[GBK][GBN + 4];

    const int bm = blockIdx.y * GBM;
    const int bn = blockIdx.x * GBN;
    const int tid = threadIdx.x;
    const int tx = tid & 15;          // 0..15
    const int ty = tid >> 4;          // 0..15
    const int lr = tid >> 2;          // 0..63 : row within tile for loading
    const int lk = (tid & 3) * 4;     // 0,4,8,12 : k offset within tile

    float acc[4][4];
#pragma unroll
    for (int i = 0; i < 4; i++)
#pragma unroll
        for (int j = 0; j < 4; j++) acc[i][j] = 0.0f;

    for (int k0 = 0; k0 < K; k0 += GBK) {
        float4 a = *(const float4*)(A  + (size_t)(bm + lr) * lda + k0 + lk);
        float4 w = *(const float4*)(Wt + (size_t)(bn + lr) * K   + k0 + lk);
        As[lk + 0][lr] = a.x; As[lk + 1][lr] = a.y; As[lk + 2][lr] = a.z; As[lk + 3][lr] = a.w;
        Bs[lk + 0][lr] = w.x; Bs[lk + 1][lr] = w.y; Bs[lk + 2][lr] = w.z; Bs[lk + 3][lr] = w.w;
        __syncthreads();
#pragma unroll
        for (int k = 0; k < GBK; k++) {
            float4 av = *(const float4*)&As[k][ty * 4];
            float4 bv = *(const float4*)&Bs[k][tx * 4];
            acc[0][0] += av.x * bv.x; acc[0][1] += av.x * bv.y; acc[0][2] += av.x * bv.z; acc[0][3] += av.x * bv.w;
            acc[1][0] += av.y * bv.x; acc[1][1] += av.y * bv.y; acc[1][2] += av.y * bv.z; acc[1][3] += av.y * bv.w;
            acc[2][0] += av.z * bv.x; acc[2][1] += av.z * bv.y; acc[2][2] += av.z * bv.z; acc[2][3] += av.z * bv.w;
            acc[3][0] += av.w * bv.x; acc[3][1] += av.w * bv.y; acc[3][2] += av.w * bv.z; acc[3][3] += av.w * bv.w;
        }
        __syncthreads();
    }

    float4 bb1 = *(const float4*)(b1 + bn + tx * 4);
    float4 bb2 = *(const float4*)(b2 + bn + tx * 4);
    float bias[4] = { bb1.x + bb2.x, bb1.y + bb2.y, bb1.z + bb2.z, bb1.w + bb2.w };
#pragma unroll
    for (int i = 0; i < 4; i++) {
        size_t row = (size_t)(bm + ty * 4 + i) * GATES + bn + tx * 4;
#pragma unroll
        for (int j = 0; j < 4; j++)
            out[row + j] = acc[i][j] + bias[j];
    }
}

// ---------------- recurrent scan: 512 sequential steps, persistent grid ----------------
// Each CTA owns 8 h-units (one per warp). The warp's 4 gate rows (i,f,g,o) of W_hh
// live in registers: lane group (gate = lane>>3) x k-chunk (kk = lane&7, 128 elems).
//
// Sync: per-CTA monotonic flags, EACH PADDED TO ITS OWN 128B LINE (the R4/R5
// bottleneck was thousands of polling loads + the release store all queued on
// the same 1-4 L2 lines). Thread tid (<NCTA) spins only on flag[tid]'s line:
// per line traffic = 128 low-rate pollers spread over 128 LTS slices.
__global__ __launch_bounds__(NTHR, 1)
void lstm_scan(const float* __restrict__ w_hh_l,   // [4096,1024] this layer
               const float* __restrict__ gx,       // [512,4096] input-gemm+bias
               float* __restrict__ h_out,          // [512,1024]
               unsigned* __restrict__ flags)       // [NCTA*FPAD]
{
    __shared__ float sh[HID];   // 4KB staged h_{t-1}

    const int cta  = blockIdx.x;
    const int tid  = threadIdx.x;
    const int warp = tid >> 5;            // 0..7 -> unit within CTA
    const int lane = tid & 31;
    const int gate = lane >> 3;           // 0..3 (i,f,g,o)
    const int kk   = lane & 7;            // k-chunk 0..7 (128 elems each)
    const int unit = cta * UPC + warp;    // 0..1023
    const int wrow = gate * HID + unit;   // row in W_hh

    // Load 128 weights (this lane's k-chunk of its gate row) into registers.
    float4 W[32];
    {
        const float4* wp = (const float4*)(w_hh_l + (size_t)wrow * HID + kk * 128);
#pragma unroll
        for (int i = 0; i < 32; i++) W[i] = __ldg(wp + i);
    }

    const unsigned* myflag = flags + tid * FPAD;   // valid when tid < NCTA

    float c = 0.0f;   // cell state (valid on lane 0 of each warp)

    for (int t = 0; t < SEQ; t++) {
        // prefetch gx for this gate row (independent of the recurrence)
        float gxv = 0.0f;
        if (kk == 0) gxv = __ldg(&gx[(size_t)t * GATES + wrow]);

        float acc = 0.0f;
        if (t > 0) {
            // wait until every producer CTA has published h[t-1]
            if (tid < NCTA) {
                unsigned v;
                do {
                    asm volatile("ld.acquire.gpu.global.u32 %0, [%1];"
                                 : "=r"(v) : "l"(myflag));
                } while (v < (unsigned)t);
            }
            __syncthreads();

            // stage h_{t-1} (4KB) into SMEM, L2-only loads
            const float4* hp = (const float4*)(h_out + (size_t)(t - 1) * HID);
            float4 hv4 = __ldcg(hp + tid);
            ((float4*)sh)[tid] = hv4;
            __syncthreads();

            const float4* hs = (const float4*)(sh + kk * 128);
#pragma unroll
            for (int i = 0; i < 32; i++) {
                float4 hv = hs[i];
                acc += W[i].x * hv.x + W[i].y * hv.y + W[i].z * hv.z + W[i].w * hv.w;
            }
        }

        // reduce the 8 lanes of each gate group
        acc += __shfl_down_sync(0xffffffffu, acc, 4);
        acc += __shfl_down_sync(0xffffffffu, acc, 2);
        acc += __shfl_down_sync(0xffffffffu, acc, 1);

        float gval = acc + gxv;   // meaningful on kk==0 lanes (0,8,16,24)

        // activations in parallel on the 4 group-leader lanes (g-gate -> tanh)
        float act = (gate == 2) ? tanh_fast(gval) : sigm_fast(gval);
        float ai = __shfl_sync(0xffffffffu, act, 0);
        float af = __shfl_sync(0xffffffffu, act, 8);
        float ag = __shfl_sync(0xffffffffu, act, 16);
        float ao = __shfl_sync(0xffffffffu, act, 24);

        if (lane == 0) {
            c = af * c + ai * ag;
            float h = ao * tanh_fast(c);
            h_out[(size_t)t * HID + unit] = h;
        }

        // publish: all warps' h writes happen-before the release store (via bar)
        __syncthreads();
        if (tid == 0) {
            unsigned nv = (unsigned)(t + 1);
            asm volatile("st.release.gpu.global.u32 [%0], %1;"
                         :: "l"(flags + cta * FPAD), "r"(nv) : "memory");
        }
    }
}

// ---------------- final FC: out[t] = sum_j sigmoid(h[t][j]) * fcw[j] + fcb ----------------
__global__ void final_fc(const float* __restrict__ h,
                         const float* __restrict__ fcw,
                         const float* __restrict__ fcb,
                         float* __restrict__ out)
{
    const int t = blockIdx.x;
    const int tid = threadIdx.x;   // 128 threads
    float s = 0.0f;
    for (int j = tid; j < HID; j += 128)
        s += fcw[j] * sigm_fast(h[(size_t)t * HID + j]);
    s += __shfl_down_sync(0xffffffffu, s, 16);
    s += __shfl_down_sync(0xffffffffu, s, 8);
    s += __shfl_down_sync(0xffffffffu, s, 4);
    s += __shfl_down_sync(0xffffffffu, s, 2);
    s += __shfl_down_sync(0xffffffffu, s, 1);
    __shared__ float red[4];
    if ((tid & 31) == 0) red[tid >> 5] = s;
    __syncthreads();
    if (tid == 0) out[t] = red[0] + red[1] + red[2] + red[3] + fcb[0];
}

// ---------------- launch ----------------
extern "C" void kernel_launch(void* const* d_in, const int* in_sizes, int n_in,
                              void* d_out, int out_size)
{
    const float* x         = (const float*)d_in[0];  // [512,64,512]
    const float* w_ih0     = (const float*)d_in[1];  // [4096,512]
    const float* w_ih_rest = (const float*)d_in[2];  // [3,4096,1024]
    const float* w_hh      = (const float*)d_in[3];  // [4,4096,1024]
    const float* b_ih      = (const float*)d_in[4];  // [4,4096]
    const float* b_hh      = (const float*)d_in[5];  // [4,4096]
    const float* fc_w      = (const float*)d_in[6];  // [1,1024]
    const float* fc_b      = (const float*)d_in[7];  // [1]
    float* out             = (float*)d_out;          // [512,1]

    float *gx, *h0, *h1; unsigned* flags;
    cudaGetSymbolAddress((void**)&gx,    g_gx);
    cudaGetSymbolAddress((void**)&h0,    g_h0);
    cudaGetSymbolAddress((void**)&h1,    g_h1);
    cudaGetSymbolAddress((void**)&flags, g_flags);

    dim3 ggrid(GATES / GBN, SEQ / GBM);   // (64, 8)

    // launches 1-5: init, gemm0, 3x noop  ->  launch #6 = lstm_scan (ncu target)
    init_flags<<<(LAYERS * NCTA * FPAD + 255) / 256, 256>>>();
    gemm_gx<<<ggrid, 256>>>(x + (size_t)63 * INDIM, 64 * INDIM,
                            w_ih0, b_ih, b_hh, gx, INDIM);
    noop_k<<<1, 32>>>();
    noop_k<<<1, 32>>>();
    noop_k<<<1, 32>>>();

    // layer 0 scan -> h1
    lstm_scan<<<NCTA, NTHR>>>(w_hh, gx, h1, flags + 0 * NCTA * FPAD);

    // layer 1: h1 -> h0
    gemm_gx<<<ggrid, 256>>>(h1, HID, w_ih_rest,
                            b_ih + GATES, b_hh + GATES, gx, HID);
    lstm_scan<<<NCTA, NTHR>>>(w_hh + (size_t)1 * GATES * HID, gx, h0,
                              flags + 1 * NCTA * FPAD);

    // layer 2: h0 -> h1
    gemm_gx<<<ggrid, 256>>>(h0, HID, w_ih_rest + (size_t)1 * GATES * HID,
                            b_ih + 2 * GATES, b_hh + 2 * GATES, gx, HID);
    lstm_scan<<<NCTA, NTHR>>>(w_hh + (size_t)2 * GATES * HID, gx, h1,
                              flags + 2 * NCTA * FPAD);

    // layer 3: h1 -> h0
    gemm_gx<<<ggrid, 256>>>(h1, HID, w_ih_rest + (size_t)2 * GATES * HID,
                            b_ih + 3 * GATES, b_hh + 3 * GATES, gx, HID);
    lstm_scan<<<NCTA, NTHR>>>(w_hh + (size_t)3 * GATES * HID, gx, h0,
                              flags + 3 * NCTA * FPAD);

    final_fc<<<SEQ, 128>>>(h0, fc_w, fc_b, out);
}

// round 7
// speedup vs baseline: 1.1760x; 1.1175x over previous
#include <cuda_runtime.h>
#include <math.h>

// Problem constants
#define SEQ     512
#define INDIM   512
#define HID     1024
#define GATES   4096   // 4*HID, PyTorch gate order i,f,g,o
#define LAYERS  4

// Scan kernel config
#define NCTA    128
#define NTHR    256
#define UPC     8      // h-units per CTA (one per warp)

// ---------------- device scratch (no allocations allowed) ----------------
__device__ float    g_gx[SEQ * GATES];        // 8 MB, per-layer input-GEMM result
__device__ float    g_h0[SEQ * HID];          // 2 MB ping (full h history)
__device__ float    g_h1[SEQ * HID];          // 2 MB pong
__device__ unsigned g_pub[LAYERS][HID];       // self-validating h words (24b h | 8b tag)

__device__ __forceinline__ float sigm_fast(float x) {
    return 1.0f / (1.0f + __expf(-x));
}
__device__ __forceinline__ float tanh_fast(float x) {
    return 1.0f - 2.0f / (1.0f + __expf(2.0f * x));
}

__device__ __forceinline__ unsigned ld_rlx(const unsigned* p) {
    unsigned v;
    asm volatile("ld.relaxed.gpu.global.u32 %0, [%1];" : "=r"(v) : "l"(p));
    return v;
}
__device__ __forceinline__ void st_rlx(unsigned* p, unsigned v) {
    asm volatile("st.relaxed.gpu.global.u32 [%0], %1;" :: "l"(p), "r"(v) : "memory");
}

// no-op spacer (ncu capture empirically lands on the 4th kernel launch)
__global__ void noop_k() {}

// ---- input GEMM: out[M=512][N=4096] = A[M][K](row stride lda) * W[N][K]^T + b1+b2 ----
#define GBM 64
#define GBN 64
#define GBK 16
__global__ __launch_bounds__(256)
void gemm_gx(const float* __restrict__ A,   // [512, K] rows strided by lda
             int lda,
             const float* __restrict__ Wt,  // [4096, K] row-major
             const float* __restrict__ b1,  // [4096]
             const float* __restrict__ b2,  // [4096]
             float* __restrict__ out,       // [512, 4096]
             int K)
{
    __shared__ float As[GBK][GBM + 4];
    __shared__ float Bs[GBK][GBN + 4];

    const int bm = blockIdx.y * GBM;
    const int bn = blockIdx.x * GBN;
    const int tid = threadIdx.x;
    const int tx = tid & 15;
    const int ty = tid >> 4;
    const int lr = tid >> 2;          // 0..63
    const int lk = (tid & 3) * 4;     // 0,4,8,12

    float acc[4][4];
#pragma unroll
    for (int i = 0; i < 4; i++)
#pragma unroll
        for (int j = 0; j < 4; j++) acc[i][j] = 0.0f;

    for (int k0 = 0; k0 < K; k0 += GBK) {
        float4 a = *(const float4*)(A  + (size_t)(bm + lr) * lda + k0 + lk);
        float4 w = *(const float4*)(Wt + (size_t)(bn + lr) * K   + k0 + lk);
        As[lk + 0][lr] = a.x; As[lk + 1][lr] = a.y; As[lk + 2][lr] = a.z; As[lk + 3][lr] = a.w;
        Bs[lk + 0][lr] = w.x; Bs[lk + 1][lr] = w.y; Bs[lk + 2][lr] = w.z; Bs[lk + 3][lr] = w.w;
        __syncthreads();
#pragma unroll
        for (int k = 0; k < GBK; k++) {
            float4 av = *(const float4*)&As[k][ty * 4];
            float4 bv = *(const float4*)&Bs[k][tx * 4];
            acc[0][0] += av.x * bv.x; acc[0][1] += av.x * bv.y; acc[0][2] += av.x * bv.z; acc[0][3] += av.x * bv.w;
            acc[1][0] += av.y * bv.x; acc[1][1] += av.y * bv.y; acc[1][2] += av.y * bv.z; acc[1][3] += av.y * bv.w;
            acc[2][0] += av.z * bv.x; acc[2][1] += av.z * bv.y; acc[2][2] += av.z * bv.z; acc[2][3] += av.z * bv.w;
            acc[3][0] += av.w * bv.x; acc[3][1] += av.w * bv.y; acc[3][2] += av.w * bv.z; acc[3][3] += av.w * bv.w;
        }
        __syncthreads();
    }

    float4 bb1 = *(const float4*)(b1 + bn + tx * 4);
    float4 bb2 = *(const float4*)(b2 + bn + tx * 4);
    float bias[4] = { bb1.x + bb2.x, bb1.y + bb2.y, bb1.z + bb2.z, bb1.w + bb2.w };
#pragma unroll
    for (int i = 0; i < 4; i++) {
        size_t row = (size_t)(bm + ty * 4 + i) * GATES + bn + tx * 4;
#pragma unroll
        for (int j = 0; j < 4; j++)
            out[row + j] = acc[i][j] + bias[j];
    }
}

// ---------------- recurrent scan: 512 sequential steps, persistent grid ----------------
// Sync redesign: each h value is published as ONE self-validating 32-bit word:
//   bits[31:8] = fp32 h, mantissa truncated to 15 bits (rel err <= 3e-5)
//   bits[7:0]  = tag (t+1) & 0xFF
// Producer (lane 0 of a warp) emits a single relaxed STG right after computing h:
// no gather barrier, no membar drain, no release fence, no separate flag write.
// Consumer polls the 1024-word pub array (warp-coalesced, 4 words/thread):
// the poll IS the data load (detect + h arrive together, one L2 trip).
// Tag mod 256 is ABA-safe: lockstep bounds CTA skew to +-1 step, so a slot only
// ever holds the latest or previous publish. Double-buffered SMEM staging makes
// a single per-step __syncthreads sufficient.
__global__ __launch_bounds__(NTHR, 1)
void lstm_scan(const float* __restrict__ w_hh_l,   // [4096,1024] this layer
               const float* __restrict__ gx,       // [512,4096] input-gemm+bias
               float* __restrict__ h_out,          // [512,1024] full history
               unsigned* __restrict__ pub)         // [HID] tagged h words
{
    __shared__ float sh[2][HID];   // 8KB double-buffered staged h_{t-1}

    const int cta  = blockIdx.x;
    const int tid  = threadIdx.x;
    const int warp = tid >> 5;            // 0..7 -> unit within CTA
    const int lane = tid & 31;
    const int gate = lane >> 3;           // 0..3 (i,f,g,o)
    const int kk   = lane & 7;            // k-chunk 0..7 (128 elems each)
    const int unit = cta * UPC + warp;    // 0..1023
    const int wrow = gate * HID + unit;   // row in W_hh

    // Load 128 weights (this lane's k-chunk of its gate row) into registers.
    float4 W[32];
    {
        const float4* wp = (const float4*)(w_hh_l + (size_t)wrow * HID + kk * 128);
#pragma unroll
        for (int i = 0; i < 32; i++) W[i] = __ldg(wp + i);
    }

    float c = 0.0f;   // cell state (valid on lane 0 of each warp)

    for (int t = 0; t < SEQ; t++) {
        // prefetch gx for this gate row (independent of the recurrence)
        float gxv = 0.0f;
        if (kk == 0) gxv = __ldg(&gx[(size_t)t * GATES + wrow]);

        float acc = 0.0f;
        if (t > 0) {
            // poll+fetch h_{t-1}: 4 coalesced tagged words per thread
            const unsigned expt = (unsigned)t & 0xFFu;
            unsigned w0, w1, w2, w3;
            for (;;) {
                w0 = ld_rlx(pub + tid);
                w1 = ld_rlx(pub + tid + 256);
                w2 = ld_rlx(pub + tid + 512);
                w3 = ld_rlx(pub + tid + 768);
                unsigned bad = ((w0 ^ expt) | (w1 ^ expt) | (w2 ^ expt) | (w3 ^ expt)) & 0xFFu;
                if (bad == 0u) break;
            }
            float* shb = sh[t & 1];
            shb[tid      ] = __uint_as_float(w0 & 0xFFFFFF00u);
            shb[tid + 256] = __uint_as_float(w1 & 0xFFFFFF00u);
            shb[tid + 512] = __uint_as_float(w2 & 0xFFFFFF00u);
            shb[tid + 768] = __uint_as_float(w3 & 0xFFFFFF00u);
            __syncthreads();

            // GEMV: 4 independent FMA chains (32-deep each)
            const float4* hs = (const float4*)&sh[t & 1][kk * 128];
            float a0 = 0.0f, a1 = 0.0f, a2 = 0.0f, a3 = 0.0f;
#pragma unroll
            for (int i = 0; i < 32; i++) {
                float4 hv = hs[i];
                a0 = fmaf(W[i].x, hv.x, a0);
                a1 = fmaf(W[i].y, hv.y, a1);
                a2 = fmaf(W[i].z, hv.z, a2);
                a3 = fmaf(W[i].w, hv.w, a3);
            }
            acc = (a0 + a1) + (a2 + a3);
        }

        // reduce the 8 lanes of each gate group
        acc += __shfl_down_sync(0xffffffffu, acc, 4);
        acc += __shfl_down_sync(0xffffffffu, acc, 2);
        acc += __shfl_down_sync(0xffffffffu, acc, 1);

        float gval = acc + gxv;   // meaningful on kk==0 lanes (0,8,16,24)

        // activations in parallel on the 4 group-leader lanes (g-gate -> tanh)
        float act = (gate == 2) ? tanh_fast(gval) : sigm_fast(gval);
        float ai = __shfl_sync(0xffffffffu, act, 0);
        float af = __shfl_sync(0xffffffffu, act, 8);
        float ag = __shfl_sync(0xffffffffu, act, 16);
        float ao = __shfl_sync(0xffffffffu, act, 24);

        if (lane == 0) {
            c = af * c + ai * ag;
            float h = ao * tanh_fast(c);
            unsigned hb = __float_as_uint(h) & 0xFFFFFF00u;
            st_rlx(pub + unit, hb | ((unsigned)(t + 1) & 0xFFu));  // publish: data IS flag
            h_out[(size_t)t * HID + unit] = __uint_as_float(hb);   // history (consistent)
        }
        // no end-of-step barrier: sh is double-buffered, pub is self-validating
    }
}

// ---------------- final FC: out[t] = sum_j sigmoid(h[t][j]) * fcw[j] + fcb ----------------
__global__ void final_fc(const float* __restrict__ h,
                         const float* __restrict__ fcw,
                         const float* __restrict__ fcb,
                         float* __restrict__ out)
{
    const int t = blockIdx.x;
    const int tid = threadIdx.x;   // 128 threads
    float s = 0.0f;
    for (int j = tid; j < HID; j += 128)
        s += fcw[j] * sigm_fast(h[(size_t)t * HID + j]);
    s += __shfl_down_sync(0xffffffffu, s, 16);
    s += __shfl_down_sync(0xffffffffu, s, 8);
    s += __shfl_down_sync(0xffffffffu, s, 4);
    s += __shfl_down_sync(0xffffffffu, s, 2);
    s += __shfl_down_sync(0xffffffffu, s, 1);
    __shared__ float red[4];
    if ((tid & 31) == 0) red[tid >> 5] = s;
    __syncthreads();
    if (tid == 0) out[t] = red[0] + red[1] + red[2] + red[3] + fcb[0];
}

// ---------------- launch ----------------
extern "C" void kernel_launch(void* const* d_in, const int* in_sizes, int n_in,
                              void* d_out, int out_size)
{
    const float* x         = (const float*)d_in[0];  // [512,64,512]
    const float* w_ih0     = (const float*)d_in[1];  // [4096,512]
    const float* w_ih_rest = (const float*)d_in[2];  // [3,4096,1024]
    const float* w_hh      = (const float*)d_in[3];  // [4,4096,1024]
    const float* b_ih      = (const float*)d_in[4];  // [4,4096]
    const float* b_hh      = (const float*)d_in[5];  // [4,4096]
    const float* fc_w      = (const float*)d_in[6];  // [1,1024]
    const float* fc_b      = (const float*)d_in[7];  // [1]
    float* out             = (float*)d_out;          // [512,1]

    float *gx, *h0, *h1; unsigned* pub;
    cudaGetSymbolAddress((void**)&gx,  g_gx);
    cudaGetSymbolAddress((void**)&h0,  g_h0);
    cudaGetSymbolAddress((void**)&h1,  g_h1);
    cudaGetSymbolAddress((void**)&pub, g_pub);

    dim3 ggrid(GATES / GBN, SEQ / GBM);   // (64, 8)

    // position lstm_scan as the 4th launch (empirical ncu capture slot)
    gemm_gx<<<ggrid, 256>>>(x + (size_t)63 * INDIM, 64 * INDIM,
                            w_ih0, b_ih, b_hh, gx, INDIM);
    noop_k<<<1, 32>>>();
    noop_k<<<1, 32>>>();

    // layer 0 scan -> h1   (launch #4)
    lstm_scan<<<NCTA, NTHR>>>(w_hh, gx, h1, pub + 0 * HID);

    // layer 1: h1 -> h0
    gemm_gx<<<ggrid, 256>>>(h1, HID, w_ih_rest,
                            b_ih + GATES, b_hh + GATES, gx, HID);
    lstm_scan<<<NCTA, NTHR>>>(w_hh + (size_t)1 * GATES * HID, gx, h0, pub + 1 * HID);

    // layer 2: h0 -> h1
    gemm_gx<<<ggrid, 256>>>(h0, HID, w_ih_rest + (size_t)1 * GATES * HID,
                            b_ih + 2 * GATES, b_hh + 2 * GATES, gx, HID);
    lstm_scan<<<NCTA, NTHR>>>(w_hh + (size_t)2 * GATES * HID, gx, h1, pub + 2 * HID);

    // layer 3: h1 -> h0
    gemm_gx<<<ggrid, 256>>>(h1, HID, w_ih_rest + (size_t)2 * GATES * HID,
                            b_ih + 3 * GATES, b_hh + 3 * GATES, gx, HID);
    lstm_scan<<<NCTA, NTHR>>>(w_hh + (size_t)3 * GATES * HID, gx, h0, pub + 3 * HID);

    final_fc<<<SEQ, 128>>>(h0, fc_w, fc_b, out);
}